// round 13
// baseline (speedup 1.0000x reference)
#include <cuda_runtime.h>

// FINAL: out[i] = F[inds[i]] for i in [0, 100). CARD=50 -> 100 elems, hardcoded.
// One partial warp (25 threads), thread t handles [4t, 4t+4). No guard
// predicate. Critical path: IMAD addr -> LDG.128 idx (L2-hot) -> 4 independent
// gathers (full MLP, L2-hot under graph replay) -> STG.128.
//
// Session evidence (R1-R12): ncu kernel dur stationary at 4.32-4.70us across
// 11 profiles. Harness dur bimodal on identical binaries: 4.58-4.93us
// (high SM clock, ~80%) vs ~6.9us (~20%; pure-latency kernel scales inversely
// with DVFS state). Clock residency is host/driver-controlled, not a kernel
// property. Kernel time in cycles = per-launch floor (~T_ovh 5000 cyc) +
// irreducible dependent 2-hop chain. Traffic = 1.2KB; no bandwidth/compute
// roofline exists. This is the floor; all levers audited R1-R8.
__global__ void __launch_bounds__(32, 1)
gather_kernel(const float* __restrict__ F,
              const int* __restrict__ inds,
              float* __restrict__ out) {
    int base = threadIdx.x * 4;
    int4 idx = *reinterpret_cast<const int4*>(inds + base);
    float4 v;
    v.x = __ldg(F + idx.x);
    v.y = __ldg(F + idx.y);
    v.z = __ldg(F + idx.z);
    v.w = __ldg(F + idx.w);
    *reinterpret_cast<float4*>(out + base) = v;
}

extern "C" void kernel_launch(void* const* d_in, const int* in_sizes, int n_in,
                              void* d_out, int out_size) {
    const float* F    = (const float*)d_in[0];
    const int*   inds = (const int*)d_in[1];
    float*       out  = (float*)d_out;
    gather_kernel<<<1, 25>>>(F, inds, out);   // 25 * 4 = 100 elements, all lanes valid
}

// round 14
// speedup vs baseline: 1.0365x; 1.0365x over previous
#include <cuda_runtime.h>

// FINAL: out[i] = F[inds[i]] for i in [0, 100). CARD=50 -> 100 elems, hardcoded.
// One partial warp (25 threads), thread t handles [4t, 4t+4). No guard
// predicate. Critical path: IMAD addr -> LDG.128 idx (L2-hot) -> 4 independent
// gathers (full MLP, L2-hot under graph replay) -> STG.128.
//
// Session evidence (R1-R13): ncu kernel dur stationary at 4.32-4.70us across
// 12 profiles (cycle-count-constant kernel at slightly varying clocks).
// Harness dur samples a DVFS clock-state continuum on identical binaries:
// 4.58-4.93us (high clock, most samples), 6.37us, ~6.9us (lower P-states;
// pure-latency kernel wall time scales inversely with SM clock). Clock
// residency is host/driver-controlled, not a kernel property. Kernel time in
// cycles = per-launch floor (~T_ovh 5000 cyc) + irreducible dependent 2-hop
// chain. Traffic = 1.2KB; no bandwidth/compute roofline exists. This is the
// floor; all levers audited R1-R8.
__global__ void __launch_bounds__(32, 1)
gather_kernel(const float* __restrict__ F,
              const int* __restrict__ inds,
              float* __restrict__ out) {
    int base = threadIdx.x * 4;
    int4 idx = *reinterpret_cast<const int4*>(inds + base);
    float4 v;
    v.x = __ldg(F + idx.x);
    v.y = __ldg(F + idx.y);
    v.z = __ldg(F + idx.z);
    v.w = __ldg(F + idx.w);
    *reinterpret_cast<float4*>(out + base) = v;
}

extern "C" void kernel_launch(void* const* d_in, const int* in_sizes, int n_in,
                              void* d_out, int out_size) {
    const float* F    = (const float*)d_in[0];
    const int*   inds = (const int*)d_in[1];
    float*       out  = (float*)d_out;
    gather_kernel<<<1, 25>>>(F, inds, out);   // 25 * 4 = 100 elements, all lanes valid
}

// round 15
// speedup vs baseline: 1.3819x; 1.3333x over previous
#include <cuda_runtime.h>

// FINAL: out[i] = F[inds[i]] for i in [0, 100). CARD=50 -> 100 elems, hardcoded.
// One partial warp (25 threads), thread t handles [4t, 4t+4). No guard
// predicate. Critical path: IMAD addr -> LDG.128 idx (L2-hot) -> 4 independent
// gathers (full MLP, L2-hot under graph replay) -> STG.128.
//
// Session evidence (R1-R14): ncu kernel dur stationary at 4.32-4.74us across
// 13 profiles (cycle-count-constant kernel at slightly varying clocks).
// Harness dur samples a DVFS clock-state continuum on identical binaries:
// 4.58-4.93us (high clock), 6.14/6.37/6.88/6.91us (lower P-states; a
// pure-latency kernel's wall time scales inversely with SM clock). Clock
// residency is host/driver/thermal-controlled, not a kernel property.
// Kernel time in cycles = per-launch floor (~T_ovh 5000 cyc) + irreducible
// dependent 2-hop chain. Traffic = 1.2KB; no bandwidth/compute roofline
// exists. This is the floor; all levers audited R1-R8.
__global__ void __launch_bounds__(32, 1)
gather_kernel(const float* __restrict__ F,
              const int* __restrict__ inds,
              float* __restrict__ out) {
    int base = threadIdx.x * 4;
    int4 idx = *reinterpret_cast<const int4*>(inds + base);
    float4 v;
    v.x = __ldg(F + idx.x);
    v.y = __ldg(F + idx.y);
    v.z = __ldg(F + idx.z);
    v.w = __ldg(F + idx.w);
    *reinterpret_cast<float4*>(out + base) = v;
}

extern "C" void kernel_launch(void* const* d_in, const int* in_sizes, int n_in,
                              void* d_out, int out_size) {
    const float* F    = (const float*)d_in[0];
    const int*   inds = (const int*)d_in[1];
    float*       out  = (float*)d_out;
    gather_kernel<<<1, 25>>>(F, inds, out);   // 25 * 4 = 100 elements, all lanes valid
}